// round 4
// baseline (speedup 1.0000x reference)
#include <cuda_runtime.h>
#include <cuda_bf16.h>

// Problem dims (fixed by the reference)
constexpr int TOKENS = 8192;
constexpr int INF    = 4096;   // in_features
constexpr int RANK   = 1024;
constexpr int OUTF   = 4096;   // out_features

// Scratch: y / y_q buffer (quantized in place), 32 MB static device global.
__device__ float g_y[(size_t)TOKENS * RANK];
__device__ int   g_amax_bits;

__global__ void k_reset() { g_amax_bits = 0; }

// ---------------------------------------------------------------------------
// GEMM1 (high accuracy): y[M,N] = A[M,K] @ B[N,K]^T, fp32 with chunked-Kahan
// accumulation. BM=128, BN=64, BK=16, 256 threads, 8x4 per-thread microtile.
// Within a BK chunk: plain fmaf into a fresh register (partial sums small ->
// tiny rounding error). Chunk sums merged into (acc, comp) via Kahan using
// __fadd_rn/__fsub_rn intrinsics (immune to fast-math reassociation).
// Net accumulation error ~1e-7 absolute on |y|~1 (vs ~1.6e-6 serial).
// Fused |y| amax reduction into g_amax_bits.
// ---------------------------------------------------------------------------
__global__ __launch_bounds__(256, 2)
void gemm1_kahan(const float* __restrict__ A, const float* __restrict__ B,
                 float* __restrict__ C, int M, int N, int K)
{
    constexpr int BM = 128, BN = 64, BK = 16;
    __shared__ float As[BK][BM];   // [k][m]
    __shared__ float Bs[BK][BN];   // [k][n]

    const int tid = threadIdx.x;
    const int tx  = tid & 15;      // n-dim, 16 threads * 4 cols = 64
    const int ty  = tid >> 4;      // m-dim, 16 threads * 8 rows = 128
    const int m0  = blockIdx.y * BM;
    const int n0  = blockIdx.x * BN;

    float acc[8][4], comp[8][4];
#pragma unroll
    for (int i = 0; i < 8; i++)
#pragma unroll
        for (int j = 0; j < 4; j++) { acc[i][j] = 0.f; comp[i][j] = 0.f; }

    const int numK = K / BK;
    for (int kt = 0; kt < numK; kt++) {
        const int k0 = kt * BK;

        // Load A tile: 128x16 = 512 float4, 2 per thread, coalesced along K.
#pragma unroll
        for (int it = 0; it < 2; it++) {
            int i   = tid + it * 256;
            int mm  = i >> 2;
            int kk4 = (i & 3) * 4;
            float4 v = *reinterpret_cast<const float4*>(
                A + (size_t)(m0 + mm) * K + k0 + kk4);
            As[kk4 + 0][mm] = v.x; As[kk4 + 1][mm] = v.y;
            As[kk4 + 2][mm] = v.z; As[kk4 + 3][mm] = v.w;
        }
        // Load B tile: 64x16 = 256 float4, 1 per thread.
        {
            int i   = tid;
            int nn  = i >> 2;
            int kk4 = (i & 3) * 4;
            float4 v = *reinterpret_cast<const float4*>(
                B + (size_t)(n0 + nn) * K + k0 + kk4);
            Bs[kk4 + 0][nn] = v.x; Bs[kk4 + 1][nn] = v.y;
            Bs[kk4 + 2][nn] = v.z; Bs[kk4 + 3][nn] = v.w;
        }
        __syncthreads();

        // Chunk accumulation (fresh registers, exact-ish for small partials).
        float chunk[8][4];
#pragma unroll
        for (int i = 0; i < 8; i++)
#pragma unroll
            for (int j = 0; j < 4; j++) chunk[i][j] = 0.f;

#pragma unroll
        for (int kk = 0; kk < BK; kk++) {
            float a[8], b[4];
            *reinterpret_cast<float4*>(&a[0]) =
                *reinterpret_cast<const float4*>(&As[kk][ty * 8]);
            *reinterpret_cast<float4*>(&a[4]) =
                *reinterpret_cast<const float4*>(&As[kk][ty * 8 + 4]);
            *reinterpret_cast<float4*>(&b[0]) =
                *reinterpret_cast<const float4*>(&Bs[kk][tx * 4]);
#pragma unroll
            for (int i = 0; i < 8; i++)
#pragma unroll
                for (int j = 0; j < 4; j++)
                    chunk[i][j] = fmaf(a[i], b[j], chunk[i][j]);
        }

        // Kahan merge: acc += chunk with compensation (explicit IEEE intrinsics).
#pragma unroll
        for (int i = 0; i < 8; i++)
#pragma unroll
            for (int j = 0; j < 4; j++) {
                float yk = __fsub_rn(chunk[i][j], comp[i][j]);
                float t  = __fadd_rn(acc[i][j], yk);
                comp[i][j] = __fsub_rn(__fsub_rn(t, acc[i][j]), yk);
                acc[i][j]  = t;
            }
        __syncthreads();
    }

    // Epilogue: fold compensation, store, fused amax.
    float lmax = 0.f;
#pragma unroll
    for (int i = 0; i < 8; i++) {
        const int m = m0 + ty * 8 + i;
        const int n = n0 + tx * 4;
        float4 v;
        v.x = __fsub_rn(acc[i][0], comp[i][0]);
        v.y = __fsub_rn(acc[i][1], comp[i][1]);
        v.z = __fsub_rn(acc[i][2], comp[i][2]);
        v.w = __fsub_rn(acc[i][3], comp[i][3]);
        *reinterpret_cast<float4*>(C + (size_t)m * N + n) = v;
        lmax = fmaxf(lmax, fmaxf(fmaxf(fabsf(v.x), fabsf(v.y)),
                                 fmaxf(fabsf(v.z), fabsf(v.w))));
    }
#pragma unroll
    for (int o = 16; o > 0; o >>= 1)
        lmax = fmaxf(lmax, __shfl_xor_sync(0xffffffffu, lmax, o));
    if ((tid & 31) == 0)
        atomicMax(&g_amax_bits, __float_as_int(lmax));   // lmax >= 0: int cmp OK

}

// ---------------------------------------------------------------------------
// GEMM2 (plain fp32): out[M,N] = A[M,K] @ B[N,K]^T + bias[n].
// BM=BN=128, BK=16, 256 threads, 8x8 microtile. Accumulation error ~8e-7
// relative -- harmless (no decision boundary downstream).
// ---------------------------------------------------------------------------
__global__ __launch_bounds__(256, 2)
void gemm2_bias(const float* __restrict__ A, const float* __restrict__ B,
                const float* __restrict__ bias, float* __restrict__ C,
                int M, int N, int K)
{
    constexpr int BM = 128, BN = 128, BK = 16;
    __shared__ float As[BK][BM];
    __shared__ float Bs[BK][BN];

    const int tid = threadIdx.x;
    const int tx  = tid & 15;
    const int ty  = tid >> 4;
    const int m0  = blockIdx.y * BM;
    const int n0  = blockIdx.x * BN;

    float acc[8][8];
#pragma unroll
    for (int i = 0; i < 8; i++)
#pragma unroll
        for (int j = 0; j < 8; j++) acc[i][j] = 0.f;

    const int numK = K / BK;
    for (int kt = 0; kt < numK; kt++) {
        const int k0 = kt * BK;
#pragma unroll
        for (int it = 0; it < 2; it++) {
            int i   = tid + it * 256;
            int mm  = i >> 2;
            int kk4 = (i & 3) * 4;
            float4 v = *reinterpret_cast<const float4*>(
                A + (size_t)(m0 + mm) * K + k0 + kk4);
            As[kk4 + 0][mm] = v.x; As[kk4 + 1][mm] = v.y;
            As[kk4 + 2][mm] = v.z; As[kk4 + 3][mm] = v.w;
        }
#pragma unroll
        for (int it = 0; it < 2; it++) {
            int i   = tid + it * 256;
            int nn  = i >> 2;
            int kk4 = (i & 3) * 4;
            float4 v = *reinterpret_cast<const float4*>(
                B + (size_t)(n0 + nn) * K + k0 + kk4);
            Bs[kk4 + 0][nn] = v.x; Bs[kk4 + 1][nn] = v.y;
            Bs[kk4 + 2][nn] = v.z; Bs[kk4 + 3][nn] = v.w;
        }
        __syncthreads();

#pragma unroll
        for (int kk = 0; kk < BK; kk++) {
            float a[8], b[8];
            *reinterpret_cast<float4*>(&a[0]) =
                *reinterpret_cast<const float4*>(&As[kk][ty * 8]);
            *reinterpret_cast<float4*>(&a[4]) =
                *reinterpret_cast<const float4*>(&As[kk][ty * 8 + 4]);
            *reinterpret_cast<float4*>(&b[0]) =
                *reinterpret_cast<const float4*>(&Bs[kk][tx * 8]);
            *reinterpret_cast<float4*>(&b[4]) =
                *reinterpret_cast<const float4*>(&Bs[kk][tx * 8 + 4]);
#pragma unroll
            for (int i = 0; i < 8; i++)
#pragma unroll
                for (int j = 0; j < 8; j++)
                    acc[i][j] = fmaf(a[i], b[j], acc[i][j]);
        }
        __syncthreads();
    }

#pragma unroll
    for (int i = 0; i < 8; i++) {
        const int m = m0 + ty * 8 + i;
#pragma unroll
        for (int j = 0; j < 8; j += 4) {
            const int n = n0 + tx * 8 + j;
            float4 v = make_float4(acc[i][j], acc[i][j + 1],
                                   acc[i][j + 2], acc[i][j + 3]);
            v.x = __fadd_rn(v.x, __ldg(bias + n));
            v.y = __fadd_rn(v.y, __ldg(bias + n + 1));
            v.z = __fadd_rn(v.z, __ldg(bias + n + 2));
            v.w = __fadd_rn(v.w, __ldg(bias + n + 3));
            *reinterpret_cast<float4*>(C + (size_t)m * N + n) = v;
        }
    }
}

// ---------------------------------------------------------------------------
// Fake-quant pass (in place): y_q = clip(round(y/scale), -4, 3) * scale.
// IEEE division + rintf (round-half-to-even) to match jnp exactly; all via
// _rn intrinsics so fast-math cannot alter semantics.
// ---------------------------------------------------------------------------
__device__ __forceinline__ float fq1(float x, float scale) {
    float q = rintf(__fdiv_rn(x, scale));
    q = fminf(fmaxf(q, -4.f), 3.f);
    return __fmul_rn(q, scale);
}

__global__ void k_quant(float* __restrict__ y, int n4) {
    const float amax  = __int_as_float(g_amax_bits);
    const float scale = __fdiv_rn(fmaxf(amax, 1e-8f), 3.0f);
    int i = blockIdx.x * blockDim.x + threadIdx.x;
    if (i < n4) {
        float4 v = reinterpret_cast<float4*>(y)[i];
        v.x = fq1(v.x, scale); v.y = fq1(v.y, scale);
        v.z = fq1(v.z, scale); v.w = fq1(v.w, scale);
        reinterpret_cast<float4*>(y)[i] = v;
    }
}

// ---------------------------------------------------------------------------
extern "C" void kernel_launch(void* const* d_in, const int* in_sizes, int n_in,
                              void* d_out, int out_size)
{
    const float* input = (const float*)d_in[0];   // [TOKENS, INF]
    const float* B_w   = (const float*)d_in[1];   // [RANK, INF]
    const float* A_w   = (const float*)d_in[2];   // [OUTF, RANK]
    const float* A_b   = (const float*)d_in[3];   // [OUTF]
    float*       out   = (float*)d_out;           // [TOKENS, OUTF]

    float* y = nullptr;
    cudaGetSymbolAddress((void**)&y, g_y);        // no alloc; capture-safe

    // 1) reset amax
    k_reset<<<1, 1>>>();

    // 2) y = input @ B_w^T  (chunked-Kahan fp32, fused amax)
    {
        dim3 grid(RANK / 64, TOKENS / 128);
        gemm1_kahan<<<grid, 256>>>(input, B_w, y, TOKENS, RANK, INF);
    }

    // 3) fake-quant in place
    {
        const int n4 = TOKENS * RANK / 4;
        k_quant<<<(n4 + 255) / 256, 256>>>(y, n4);
    }

    // 4) out = y_q @ A_w^T + A_b  (plain fp32, fused bias)
    {
        dim3 grid(OUTF / 128, TOKENS / 128);
        gemm2_bias<<<grid, 256>>>(y, A_w, A_b, out, TOKENS, OUTF, RANK);
    }
}

// round 6
// speedup vs baseline: 2.2544x; 2.2544x over previous
#include <cuda_runtime.h>
#include <cuda_bf16.h>
#include <cstdint>

constexpr int TOKENS = 8192;
constexpr int INF    = 4096;
constexpr int RANK   = 1024;
constexpr int OUTF   = 4096;

// ---------------- static device scratch (no allocs allowed) ----------------
__device__ __nv_bfloat16 g_x1[(size_t)TOKENS * INF];
__device__ __nv_bfloat16 g_x2[(size_t)TOKENS * INF];
__device__ __nv_bfloat16 g_x3[(size_t)TOKENS * INF];
__device__ __nv_bfloat16 g_w1[(size_t)RANK * INF];
__device__ __nv_bfloat16 g_w2[(size_t)RANK * INF];
__device__ __nv_bfloat16 g_w3[(size_t)RANK * INF];
__device__ __nv_bfloat16 g_a1[(size_t)OUTF * RANK];
__device__ __nv_bfloat16 g_a2[(size_t)OUTF * RANK];
__device__ __nv_bfloat16 g_q [(size_t)TOKENS * RANK];
__device__ float         g_y [(size_t)TOKENS * RANK];
__device__ int           g_amax_bits;

// ---------------- low-level helpers (all baseline PTX, sm_80+) ----------------
__device__ __forceinline__ uint32_t smem_u32(const void* p) {
    uint32_t a;
    asm("{ .reg .u64 t; cvta.to.shared.u64 t, %1; cvt.u32.u64 %0, t; }" : "=r"(a) : "l"(p));
    return a;
}
__device__ __forceinline__ void cpa16(uint32_t s, const void* g) {
    asm volatile("cp.async.cg.shared.global [%0], [%1], 16;" :: "r"(s), "l"(g));
}
__device__ __forceinline__ void cpa_commit() { asm volatile("cp.async.commit_group;" ::: "memory"); }
__device__ __forceinline__ void cpa_wait1()  { asm volatile("cp.async.wait_group 1;" ::: "memory"); }
__device__ __forceinline__ void cpa_wait0()  { asm volatile("cp.async.wait_group 0;" ::: "memory"); }

__device__ __forceinline__ void ldsm4(uint32_t* r, uint32_t a) {
    asm volatile("ldmatrix.sync.aligned.m8n8.x4.shared.b16 {%0,%1,%2,%3}, [%4];"
                 : "=r"(r[0]), "=r"(r[1]), "=r"(r[2]), "=r"(r[3]) : "r"(a));
}
__device__ __forceinline__ void ldsm2(uint32_t* r, uint32_t a) {
    asm volatile("ldmatrix.sync.aligned.m8n8.x2.shared.b16 {%0,%1}, [%2];"
                 : "=r"(r[0]), "=r"(r[1]) : "r"(a));
}
__device__ __forceinline__ void mma_bf16(float* d, const uint32_t* a, const uint32_t* b) {
    asm volatile(
        "mma.sync.aligned.m16n8k16.row.col.f32.bf16.bf16.f32 "
        "{%0,%1,%2,%3}, {%4,%5,%6,%7}, {%8,%9}, {%0,%1,%2,%3};"
        : "+f"(d[0]), "+f"(d[1]), "+f"(d[2]), "+f"(d[3])
        : "r"(a[0]), "r"(a[1]), "r"(a[2]), "r"(a[3]), "r"(b[0]), "r"(b[1]));
}
// 128B rows of 8 x 16B chunks; xor-swizzle -> conflict-free ldmatrix & stores
__device__ __forceinline__ uint32_t sw(uint32_t row, uint32_t ch) {
    return row * 128u + ((ch ^ (row & 7u)) * 16u);
}

// ---------------- prep kernels ----------------
__global__ void k_reset() { g_amax_bits = 0; }

__global__ void k_split3(const float* __restrict__ s, __nv_bfloat16* __restrict__ d1,
                         __nv_bfloat16* __restrict__ d2, __nv_bfloat16* __restrict__ d3, int n2) {
    int i = blockIdx.x * blockDim.x + threadIdx.x;
    if (i >= n2) return;
    float2 v = reinterpret_cast<const float2*>(s)[i];
    float f[2] = {v.x, v.y};
    __nv_bfloat16 h1[2], h2[2], h3[2];
#pragma unroll
    for (int j = 0; j < 2; j++) {
        h1[j] = __float2bfloat16_rn(f[j]);
        float r  = __fsub_rn(f[j], __bfloat162float(h1[j]));   // exact
        h2[j] = __float2bfloat16_rn(r);
        float r2 = __fsub_rn(r, __bfloat162float(h2[j]));      // exact
        h3[j] = __float2bfloat16_rn(r2);                       // exact
    }
    reinterpret_cast<__nv_bfloat162*>(d1)[i] = __halves2bfloat162(h1[0], h1[1]);
    reinterpret_cast<__nv_bfloat162*>(d2)[i] = __halves2bfloat162(h2[0], h2[1]);
    reinterpret_cast<__nv_bfloat162*>(d3)[i] = __halves2bfloat162(h3[0], h3[1]);
}

__global__ void k_split2(const float* __restrict__ s, __nv_bfloat16* __restrict__ d1,
                         __nv_bfloat16* __restrict__ d2, int n2) {
    int i = blockIdx.x * blockDim.x + threadIdx.x;
    if (i >= n2) return;
    float2 v = reinterpret_cast<const float2*>(s)[i];
    float f[2] = {v.x, v.y};
    __nv_bfloat16 h1[2], h2[2];
#pragma unroll
    for (int j = 0; j < 2; j++) {
        h1[j] = __float2bfloat16_rn(f[j]);
        float r = __fsub_rn(f[j], __bfloat162float(h1[j]));
        h2[j] = __float2bfloat16_rn(r);
    }
    reinterpret_cast<__nv_bfloat162*>(d1)[i] = __halves2bfloat162(h1[0], h1[1]);
    reinterpret_cast<__nv_bfloat162*>(d2)[i] = __halves2bfloat162(h2[0], h2[1]);
}

// q = clip(round(y/scale), -4, 3), exact small integers in bf16
__global__ void k_quant(const float* __restrict__ y, __nv_bfloat16* __restrict__ q, int n2) {
    const float amax  = __int_as_float(g_amax_bits);
    const float scale = __fdiv_rn(fmaxf(amax, 1e-8f), 3.0f);
    int i = blockIdx.x * blockDim.x + threadIdx.x;
    if (i >= n2) return;
    float2 v = reinterpret_cast<const float2*>(y)[i];
    float q0 = fminf(fmaxf(rintf(__fdiv_rn(v.x, scale)), -4.f), 3.f);
    float q1 = fminf(fmaxf(rintf(__fdiv_rn(v.y, scale)), -4.f), 3.f);
    reinterpret_cast<__nv_bfloat162*>(q)[i] =
        __halves2bfloat162(__float2bfloat16_rn(q0), __float2bfloat16_rn(q1));
}

// ---------------------------------------------------------------------------
// GEMM1: y = x @ B_w^T via 6 limb products on mma.sync bf16.
// Block 128(M)x64(N), BK=64, 512 threads = 16 warps (4m x 4n), warp tile 32x16.
// Per k-tile: fresh chunk accum (all 6 products, small->big order), Kahan merge.
// ---------------------------------------------------------------------------
constexpr int G1_STAGE = 3 * 16384 + 3 * 8192;   // x1,x2,x3 (128x64) + w1,w2,w3 (64x64)
constexpr int G1_SMEM  = 2 * G1_STAGE;           // 144 KB

__global__ __launch_bounds__(512, 1)
void gemm1_mma(const __nv_bfloat16* __restrict__ X1, const __nv_bfloat16* __restrict__ X2,
               const __nv_bfloat16* __restrict__ X3, const __nv_bfloat16* __restrict__ W1,
               const __nv_bfloat16* __restrict__ W2, const __nv_bfloat16* __restrict__ W3,
               float* __restrict__ Y)
{
    extern __shared__ char smem_raw[];
    const uint32_t sbu = smem_u32(smem_raw);
    const int tid = threadIdx.x, lane = tid & 31, wid = tid >> 5;
    const int wm = wid & 3, wn = wid >> 2;
    const int m0 = blockIdx.y * 128, n0 = blockIdx.x * 64;

    const __nv_bfloat16* AP[3] = {X1, X2, X3};
    const __nv_bfloat16* BP[3] = {W1, W2, W3};

    float acc[16], cmp[16];
#pragma unroll
    for (int c = 0; c < 16; c++) { acc[c] = 0.f; cmp[c] = 0.f; }

    // ---- stage loader ----
    auto load_stage = [&](int kt, int buf) {
        const uint32_t sb = sbu + buf * G1_STAGE;
        const int k0 = kt * 64;
#pragma unroll
        for (int l = 0; l < 3; l++) {
#pragma unroll
            for (int it = 0; it < 2; it++) {            // A tile: 1024 chunks
                int i = tid + it * 512;
                int row = i >> 3, ch = i & 7;
                cpa16(sb + l * 16384 + sw(row, ch),
                      AP[l] + (size_t)(m0 + row) * INF + k0 + ch * 8);
            }
            {                                            // B tile: 512 chunks
                int row = tid >> 3, ch = tid & 7;
                cpa16(sb + 49152 + l * 8192 + sw(row, ch),
                      BP[l] + (size_t)(n0 + row) * INF + k0 + ch * 8);
            }
        }
        cpa_commit();
    };

    load_stage(0, 0);

    for (int kt = 0; kt < 64; kt++) {
        const int buf = kt & 1;
        if (kt < 63) { load_stage(kt + 1, buf ^ 1); cpa_wait1(); }
        else         { cpa_wait0(); }
        __syncthreads();

        const uint32_t sb = sbu + buf * G1_STAGE;
        float chunk[16];
#pragma unroll
        for (int c = 0; c < 16; c++) chunk[c] = 0.f;

        const int tA = lane >> 3, rA = lane & 7;
        const int lB = lane & 15;
        // products grouped by A-limb, small-magnitude first, (1,1) last
        for (int al = 2; al >= 0; al--) {
            uint32_t aF[2][4][4];
            const uint32_t ta = sb + al * 16384;
#pragma unroll
            for (int mi = 0; mi < 2; mi++)
#pragma unroll
                for (int ks = 0; ks < 4; ks++) {
                    uint32_t row = wm * 32 + mi * 16 + (tA & 1) * 8 + rA;
                    uint32_t ch  = ks * 2 + (tA >> 1);
                    ldsm4(aF[mi][ks], ta + sw(row, ch));
                }
            const int nb = (al == 0) ? 3 : (al == 1 ? 2 : 1);
            for (int bl = nb - 1; bl >= 0; bl--) {
                const uint32_t tb = sb + 49152 + bl * 8192;
#pragma unroll
                for (int ks = 0; ks < 4; ks++)
#pragma unroll
                    for (int ni = 0; ni < 2; ni++) {
                        uint32_t bF[2];
                        uint32_t row = wn * 16 + ni * 8 + (lB & 7);
                        uint32_t ch  = ks * 2 + (lB >> 3);
                        ldsm2(bF, tb + sw(row, ch));
                        mma_bf16(&chunk[ni * 4],     aF[0][ks], bF);
                        mma_bf16(&chunk[8 + ni * 4], aF[1][ks], bF);
                    }
            }
        }
        // Kahan merge (IEEE intrinsics; immune to fast-math)
#pragma unroll
        for (int c = 0; c < 16; c++) {
            float yk = __fsub_rn(chunk[c], cmp[c]);
            float t  = __fadd_rn(acc[c], yk);
            cmp[c]   = __fsub_rn(__fsub_rn(t, acc[c]), yk);
            acc[c]   = t;
        }
        __syncthreads();
    }

    // ---- epilogue: fold, amax, store ----
    float v[16];
    float lmax = 0.f;
#pragma unroll
    for (int c = 0; c < 16; c++) {
        v[c] = __fsub_rn(acc[c], cmp[c]);
        lmax = fmaxf(lmax, fabsf(v[c]));
    }
#pragma unroll
    for (int o = 16; o > 0; o >>= 1)
        lmax = fmaxf(lmax, __shfl_xor_sync(0xffffffffu, lmax, o));
    if (lane == 0) atomicMax(&g_amax_bits, __float_as_int(lmax));

    const int rbase = m0 + wm * 32 + (lane >> 2);
    const int cbase = n0 + wn * 16 + (lane & 3) * 2;
#pragma unroll
    for (int mi = 0; mi < 2; mi++)
#pragma unroll
        for (int ni = 0; ni < 2; ni++) {
            const float* f = &v[mi * 8 + ni * 4];
            float* p0 = Y + (size_t)(rbase + mi * 16)     * RANK + cbase + ni * 8;
            float* p1 = Y + (size_t)(rbase + mi * 16 + 8) * RANK + cbase + ni * 8;
            *reinterpret_cast<float2*>(p0) = make_float2(f[0], f[1]);
            *reinterpret_cast<float2*>(p1) = make_float2(f[2], f[3]);
        }
}

// ---------------------------------------------------------------------------
// GEMM2: out = (q @ A^T) * scale + bias, 2 limb products, plain accumulation.
// Same geometry: block 128x64, BK=64, 512 threads, warp tile 32x16.
// ---------------------------------------------------------------------------
constexpr int G2_STAGE = 16384 + 2 * 8192;   // q (128x64) + a1,a2 (64x64)
constexpr int G2_SMEM  = 2 * G2_STAGE;       // 64 KB

__global__ __launch_bounds__(512, 1)
void gemm2_mma(const __nv_bfloat16* __restrict__ Q, const __nv_bfloat16* __restrict__ A1,
               const __nv_bfloat16* __restrict__ A2, const float* __restrict__ bias,
               float* __restrict__ Out)
{
    extern __shared__ char smem_raw[];
    const uint32_t sbu = smem_u32(smem_raw);
    const int tid = threadIdx.x, lane = tid & 31, wid = tid >> 5;
    const int wm = wid & 3, wn = wid >> 2;
    const int m0 = blockIdx.y * 128, n0 = blockIdx.x * 64;

    const __nv_bfloat16* BP[2] = {A1, A2};

    float acc[16];
#pragma unroll
    for (int c = 0; c < 16; c++) acc[c] = 0.f;

    auto load_stage = [&](int kt, int buf) {
        const uint32_t sb = sbu + buf * G2_STAGE;
        const int k0 = kt * 64;
#pragma unroll
        for (int it = 0; it < 2; it++) {              // Q tile
            int i = tid + it * 512;
            int row = i >> 3, ch = i & 7;
            cpa16(sb + sw(row, ch), Q + (size_t)(m0 + row) * RANK + k0 + ch * 8);
        }
#pragma unroll
        for (int l = 0; l < 2; l++) {                 // A limb tiles
            int row = tid >> 3, ch = tid & 7;
            cpa16(sb + 16384 + l * 8192 + sw(row, ch),
                  BP[l] + (size_t)(n0 + row) * RANK + k0 + ch * 8);
        }
        cpa_commit();
    };

    load_stage(0, 0);

    for (int kt = 0; kt < 16; kt++) {
        const int buf = kt & 1;
        if (kt < 15) { load_stage(kt + 1, buf ^ 1); cpa_wait1(); }
        else         { cpa_wait0(); }
        __syncthreads();

        const uint32_t sb = sbu + buf * G2_STAGE;
        const int tA = lane >> 3, rA = lane & 7;
        const int lB = lane & 15;

        uint32_t aF[2][4][4];
#pragma unroll
        for (int mi = 0; mi < 2; mi++)
#pragma unroll
            for (int ks = 0; ks < 4; ks++) {
                uint32_t row = wm * 32 + mi * 16 + (tA & 1) * 8 + rA;
                uint32_t ch  = ks * 2 + (tA >> 1);
                ldsm4(aF[mi][ks], sb + sw(row, ch));
            }
#pragma unroll
        for (int bl = 1; bl >= 0; bl--) {
            const uint32_t tb = sb + 16384 + bl * 8192;
#pragma unroll
            for (int ks = 0; ks < 4; ks++)
#pragma unroll
                for (int ni = 0; ni < 2; ni++) {
                    uint32_t bF[2];
                    uint32_t row = wn * 16 + ni * 8 + (lB & 7);
                    uint32_t ch  = ks * 2 + (lB >> 3);
                    ldsm2(bF, tb + sw(row, ch));
                    mma_bf16(&acc[ni * 4],     aF[0][ks], bF);
                    mma_bf16(&acc[8 + ni * 4], aF[1][ks], bF);
                }
        }
        __syncthreads();
    }

    // ---- epilogue: scale + bias ----
    const float amax  = __int_as_float(g_amax_bits);
    const float scale = __fdiv_rn(fmaxf(amax, 1e-8f), 3.0f);
    const int rbase = m0 + wm * 32 + (lane >> 2);
    const int cbase = n0 + wn * 16 + (lane & 3) * 2;
#pragma unroll
    for (int mi = 0; mi < 2; mi++)
#pragma unroll
        for (int ni = 0; ni < 2; ni++) {
            const float* f = &acc[mi * 8 + ni * 4];
            const int col = cbase + ni * 8;
            const float b0 = __ldg(bias + col), b1 = __ldg(bias + col + 1);
            float* p0 = Out + (size_t)(rbase + mi * 16)     * OUTF + col;
            float* p1 = Out + (size_t)(rbase + mi * 16 + 8) * OUTF + col;
            *reinterpret_cast<float2*>(p0) =
                make_float2(__fadd_rn(__fmul_rn(f[0], scale), b0),
                            __fadd_rn(__fmul_rn(f[1], scale), b1));
            *reinterpret_cast<float2*>(p1) =
                make_float2(__fadd_rn(__fmul_rn(f[2], scale), b0),
                            __fadd_rn(__fmul_rn(f[3], scale), b1));
        }
}

// ---------------------------------------------------------------------------
extern "C" void kernel_launch(void* const* d_in, const int* in_sizes, int n_in,
                              void* d_out, int out_size)
{
    const float* input = (const float*)d_in[0];
    const float* B_w   = (const float*)d_in[1];
    const float* A_w   = (const float*)d_in[2];
    const float* A_b   = (const float*)d_in[3];
    float*       out   = (float*)d_out;

    __nv_bfloat16 *x1, *x2, *x3, *w1, *w2, *w3, *a1, *a2, *q;
    float* y;
    cudaGetSymbolAddress((void**)&x1, g_x1); cudaGetSymbolAddress((void**)&x2, g_x2);
    cudaGetSymbolAddress((void**)&x3, g_x3); cudaGetSymbolAddress((void**)&w1, g_w1);
    cudaGetSymbolAddress((void**)&w2, g_w2); cudaGetSymbolAddress((void**)&w3, g_w3);
    cudaGetSymbolAddress((void**)&a1, g_a1); cudaGetSymbolAddress((void**)&a2, g_a2);
    cudaGetSymbolAddress((void**)&q,  g_q);  cudaGetSymbolAddress((void**)&y,  g_y);

    cudaFuncSetAttribute(gemm1_mma, cudaFuncAttributeMaxDynamicSharedMemorySize, G1_SMEM);
    cudaFuncSetAttribute(gemm2_mma, cudaFuncAttributeMaxDynamicSharedMemorySize, G2_SMEM);

    k_reset<<<1, 1>>>();

    {   // limb splits
        int n2 = TOKENS * INF / 2;
        k_split3<<<(n2 + 255) / 256, 256>>>(input, x1, x2, x3, n2);
        n2 = RANK * INF / 2;
        k_split3<<<(n2 + 255) / 256, 256>>>(B_w, w1, w2, w3, n2);
        n2 = OUTF * RANK / 2;
        k_split2<<<(n2 + 255) / 256, 256>>>(A_w, a1, a2, n2);
    }

    {   // y = x @ B_w^T  (tensor cores, fused amax)
        dim3 grid(RANK / 64, TOKENS / 128);
        gemm1_mma<<<grid, 512, G1_SMEM>>>(x1, x2, x3, w1, w2, w3, y);
    }

    {   // q = clip(round(y/scale))
        const int n2 = TOKENS * RANK / 2;
        k_quant<<<(n2 + 255) / 256, 256>>>(y, q, n2);
    }

    {   // out = q @ A^T * scale + bias
        dim3 grid(OUTF / 64, TOKENS / 128);
        gemm2_mma<<<grid, 512, G2_SMEM>>>(q, a1, a2, A_b, out);
    }
}

// round 8
// speedup vs baseline: 2.6728x; 1.1856x over previous
#include <cuda_runtime.h>
#include <cuda_bf16.h>
#include <cstdint>

constexpr int TOKENS = 8192;
constexpr int INF    = 4096;
constexpr int RANK   = 1024;
constexpr int OUTF   = 4096;

// ---------------- static device scratch (no allocs allowed) ----------------
__device__ __nv_bfloat16 g_x1[(size_t)TOKENS * INF];
__device__ __nv_bfloat16 g_x2[(size_t)TOKENS * INF];
__device__ __nv_bfloat16 g_x3[(size_t)TOKENS * INF];
__device__ __nv_bfloat16 g_w1[(size_t)RANK * INF];
__device__ __nv_bfloat16 g_w2[(size_t)RANK * INF];
__device__ __nv_bfloat16 g_w3[(size_t)RANK * INF];
__device__ __nv_bfloat16 g_a1[(size_t)OUTF * RANK];
__device__ __nv_bfloat16 g_a2[(size_t)OUTF * RANK];
__device__ __nv_bfloat16 g_q [(size_t)TOKENS * RANK];
__device__ float         g_y [(size_t)TOKENS * RANK];
__device__ int           g_amax_bits;

// ---------------- low-level helpers (baseline PTX, sm_80+) ----------------
__device__ __forceinline__ uint32_t smem_u32(const void* p) {
    uint32_t a;
    asm("{ .reg .u64 t; cvta.to.shared.u64 t, %1; cvt.u32.u64 %0, t; }" : "=r"(a) : "l"(p));
    return a;
}
__device__ __forceinline__ void cpa16(uint32_t s, const void* g) {
    asm volatile("cp.async.cg.shared.global [%0], [%1], 16;" :: "r"(s), "l"(g));
}
__device__ __forceinline__ void cpa_commit() { asm volatile("cp.async.commit_group;" ::: "memory"); }
__device__ __forceinline__ void cpa_wait1()  { asm volatile("cp.async.wait_group 1;" ::: "memory"); }

__device__ __forceinline__ void ldsm4(uint32_t* r, uint32_t a) {
    asm volatile("ldmatrix.sync.aligned.m8n8.x4.shared.b16 {%0,%1,%2,%3}, [%4];"
                 : "=r"(r[0]), "=r"(r[1]), "=r"(r[2]), "=r"(r[3]) : "r"(a));
}
__device__ __forceinline__ void mma_bf16(float* d, const uint32_t* a, const uint32_t* b) {
    asm volatile(
        "mma.sync.aligned.m16n8k16.row.col.f32.bf16.bf16.f32 "
        "{%0,%1,%2,%3}, {%4,%5,%6,%7}, {%8,%9}, {%0,%1,%2,%3};"
        : "+f"(d[0]), "+f"(d[1]), "+f"(d[2]), "+f"(d[3])
        : "r"(a[0]), "r"(a[1]), "r"(a[2]), "r"(a[3]), "r"(b[0]), "r"(b[1]));
}
// 128B rows of 8 x 16B chunks; xor-swizzle -> conflict-free ldmatrix & stores
__device__ __forceinline__ uint32_t sw(uint32_t row, uint32_t ch) {
    return row * 128u + ((ch ^ (row & 7u)) * 16u);
}

// ---------------- prep kernels ----------------
__global__ void k_reset() { g_amax_bits = 0; }

__global__ void k_split3(const float* __restrict__ s, __nv_bfloat16* __restrict__ d1,
                         __nv_bfloat16* __restrict__ d2, __nv_bfloat16* __restrict__ d3, int n2) {
    int i = blockIdx.x * blockDim.x + threadIdx.x;
    if (i >= n2) return;
    float2 v = reinterpret_cast<const float2*>(s)[i];
    float f[2] = {v.x, v.y};
    __nv_bfloat16 h1[2], h2[2], h3[2];
#pragma unroll
    for (int j = 0; j < 2; j++) {
        h1[j] = __float2bfloat16_rn(f[j]);
        float r  = __fsub_rn(f[j], __bfloat162float(h1[j]));   // exact
        h2[j] = __float2bfloat16_rn(r);
        float r2 = __fsub_rn(r, __bfloat162float(h2[j]));      // exact
        h3[j] = __float2bfloat16_rn(r2);                       // exact (27>=24 bits)
    }
    reinterpret_cast<__nv_bfloat162*>(d1)[i] = __halves2bfloat162(h1[0], h1[1]);
    reinterpret_cast<__nv_bfloat162*>(d2)[i] = __halves2bfloat162(h2[0], h2[1]);
    reinterpret_cast<__nv_bfloat162*>(d3)[i] = __halves2bfloat162(h3[0], h3[1]);
}

__global__ void k_split2(const float* __restrict__ s, __nv_bfloat16* __restrict__ d1,
                         __nv_bfloat16* __restrict__ d2, int n2) {
    int i = blockIdx.x * blockDim.x + threadIdx.x;
    if (i >= n2) return;
    float2 v = reinterpret_cast<const float2*>(s)[i];
    float f[2] = {v.x, v.y};
    __nv_bfloat16 h1[2], h2[2];
#pragma unroll
    for (int j = 0; j < 2; j++) {
        h1[j] = __float2bfloat16_rn(f[j]);
        float r = __fsub_rn(f[j], __bfloat162float(h1[j]));
        h2[j] = __float2bfloat16_rn(r);
    }
    reinterpret_cast<__nv_bfloat162*>(d1)[i] = __halves2bfloat162(h1[0], h1[1]);
    reinterpret_cast<__nv_bfloat162*>(d2)[i] = __halves2bfloat162(h2[0], h2[1]);
}

// q = clip(round(y/scale), -4, 3), exact small integers in bf16
__global__ void k_quant(const float* __restrict__ y, __nv_bfloat16* __restrict__ q, int n2) {
    const float amax  = __int_as_float(g_amax_bits);
    const float scale = __fdiv_rn(fmaxf(amax, 1e-8f), 3.0f);
    int i = blockIdx.x * blockDim.x + threadIdx.x;
    if (i >= n2) return;
    float2 v = reinterpret_cast<const float2*>(y)[i];
    float q0 = fminf(fmaxf(rintf(__fdiv_rn(v.x, scale)), -4.f), 3.f);
    float q1 = fminf(fmaxf(rintf(__fdiv_rn(v.y, scale)), -4.f), 3.f);
    reinterpret_cast<__nv_bfloat162*>(q)[i] =
        __halves2bfloat162(__float2bfloat16_rn(q0), __float2bfloat16_rn(q1));
}

// ---------------------------------------------------------------------------
// GEMM1: y = x @ B_w^T via 6 limb products on mma.sync bf16.
// Block 128(M)x64(N), BK=64, 512 threads = 16 warps (4m x 4n), warp tile 32x16.
// 3-stage cp.async pipeline, 1 sync/k-tile. Fresh chunk per k-tile (K=64),
// Kahan-merged every k-tile (IEEE intrinsics) -- numerics identical to R6.
// ---------------------------------------------------------------------------
constexpr int G1_STAGE = 3 * 16384 + 3 * 8192;   // x limbs (128x64) + w limbs (64x64)
constexpr int G1_SMEM  = 3 * G1_STAGE;           // 216 KB

__global__ __launch_bounds__(512, 1)
void gemm1_mma(const __nv_bfloat16* __restrict__ X1, const __nv_bfloat16* __restrict__ X2,
               const __nv_bfloat16* __restrict__ X3, const __nv_bfloat16* __restrict__ W1,
               const __nv_bfloat16* __restrict__ W2, const __nv_bfloat16* __restrict__ W3,
               float* __restrict__ Y)
{
    extern __shared__ char smem_raw[];
    const uint32_t sbu = smem_u32(smem_raw);
    const int tid = threadIdx.x, lane = tid & 31, wid = tid >> 5;
    const int wm = wid & 3, wn = wid >> 2;
    const int m0 = blockIdx.y * 128, n0 = blockIdx.x * 64;

    const __nv_bfloat16* AP[3] = {X1, X2, X3};
    const __nv_bfloat16* BP[3] = {W1, W2, W3};

    float acc[16], cmp[16];
#pragma unroll
    for (int c = 0; c < 16; c++) { acc[c] = 0.f; cmp[c] = 0.f; }

    auto load_stage = [&](int kt, int buf) {
        const uint32_t sb = sbu + buf * G1_STAGE;
        const int k0 = kt * 64;
#pragma unroll
        for (int l = 0; l < 3; l++) {
#pragma unroll
            for (int it = 0; it < 2; it++) {            // A tile: 1024 chunks
                int i = tid + it * 512;
                int row = i >> 3, ch = i & 7;
                cpa16(sb + l * 16384 + sw(row, ch),
                      AP[l] + (size_t)(m0 + row) * INF + k0 + ch * 8);
            }
            {                                            // B tile: 512 chunks
                int row = tid >> 3, ch = tid & 7;
                cpa16(sb + 49152 + l * 8192 + sw(row, ch),
                      BP[l] + (size_t)(n0 + row) * INF + k0 + ch * 8);
            }
        }
    };

    load_stage(0, 0); cpa_commit();
    load_stage(1, 1); cpa_commit();

    const int tA = lane >> 3, rA = lane & 7;
    const uint32_t arow = wm * 32 + (tA & 1) * 8 + rA;      // + mi*16
    const uint32_t brow = wn * 16 + ((lane >> 4) & 1) * 8 + (lane & 7);  // x4-B row
    const uint32_t bch  = (lane >> 3) & 1;                  // + ks*2

    for (int kt = 0; kt < 64; kt++) {
        cpa_wait1();
        __syncthreads();

        const uint32_t sb = sbu + (kt % 3) * G1_STAGE;
        float chunk[16];
#pragma unroll
        for (int c = 0; c < 16; c++) chunk[c] = 0.f;

        // products grouped by A-limb, small-magnitude first, (1,1) last
#pragma unroll
        for (int al = 2; al >= 0; al--) {
            uint32_t aF[2][4][4];
            const uint32_t ta = sb + al * 16384;
#pragma unroll
            for (int mi = 0; mi < 2; mi++)
#pragma unroll
                for (int ks = 0; ks < 4; ks++)
                    ldsm4(aF[mi][ks], ta + sw(arow + mi * 16, ks * 2 + (tA >> 1)));
            const int nb = (al == 0) ? 3 : (al == 1 ? 2 : 1);
#pragma unroll
            for (int bl = 2; bl >= 0; bl--) {
                if (bl >= nb) continue;
                const uint32_t tb = sb + 49152 + bl * 8192;
#pragma unroll
                for (int ks = 0; ks < 4; ks++) {
                    uint32_t bF[4];                      // [ni0 k0,k1, ni1 k0,k1]
                    ldsm4(bF, tb + sw(brow, ks * 2 + bch));
                    mma_bf16(&chunk[0],  aF[0][ks], bF + 0);
                    mma_bf16(&chunk[8],  aF[1][ks], bF + 0);
                    mma_bf16(&chunk[4],  aF[0][ks], bF + 2);
                    mma_bf16(&chunk[12], aF[1][ks], bF + 2);
                }
            }
        }

        // Kahan merge every k-tile (IEEE intrinsics; immune to fast-math)
#pragma unroll
        for (int c = 0; c < 16; c++) {
            float yk = __fsub_rn(chunk[c], cmp[c]);
            float t  = __fadd_rn(acc[c], yk);
            cmp[c]   = __fsub_rn(__fsub_rn(t, acc[c]), yk);
            acc[c]   = t;
        }

        if (kt + 2 < 64) load_stage(kt + 2, (kt + 2) % 3);
        cpa_commit();          // empty group at tail keeps wait_group bookkeeping
    }

    // ---- epilogue: fold, amax, store ----
    float v[16];
    float lmax = 0.f;
#pragma unroll
    for (int c = 0; c < 16; c++) {
        v[c] = __fsub_rn(acc[c], cmp[c]);
        lmax = fmaxf(lmax, fabsf(v[c]));
    }
#pragma unroll
    for (int o = 16; o > 0; o >>= 1)
        lmax = fmaxf(lmax, __shfl_xor_sync(0xffffffffu, lmax, o));
    if (lane == 0) atomicMax(&g_amax_bits, __float_as_int(lmax));

    const int rbase = m0 + wm * 32 + (lane >> 2);
    const int cbase = n0 + wn * 16 + (lane & 3) * 2;
#pragma unroll
    for (int mi = 0; mi < 2; mi++)
#pragma unroll
        for (int ni = 0; ni < 2; ni++) {
            const float* f = &v[mi * 8 + ni * 4];
            float* p0 = Y + (size_t)(rbase + mi * 16)     * RANK + cbase + ni * 8;
            float* p1 = Y + (size_t)(rbase + mi * 16 + 8) * RANK + cbase + ni * 8;
            *reinterpret_cast<float2*>(p0) = make_float2(f[0], f[1]);
            *reinterpret_cast<float2*>(p1) = make_float2(f[2], f[3]);
        }
}

// ---------------------------------------------------------------------------
// GEMM2: out = (q @ A^T) * scale + bias, 2 limb products, plain accumulation.
// Block 128x64, BK=64, 512 threads, warp tile 32x16, 3-stage pipeline.
// ---------------------------------------------------------------------------
constexpr int G2_STAGE = 16384 + 2 * 8192;   // q (128x64) + a1,a2 (64x64)
constexpr int G2_SMEM  = 3 * G2_STAGE;       // 96 KB

__global__ __launch_bounds__(512, 1)
void gemm2_mma(const __nv_bfloat16* __restrict__ Q, const __nv_bfloat16* __restrict__ A1,
               const __nv_bfloat16* __restrict__ A2, const float* __restrict__ bias,
               float* __restrict__ Out)
{
    extern __shared__ char smem_raw[];
    const uint32_t sbu = smem_u32(smem_raw);
    const int tid = threadIdx.x, lane = tid & 31, wid = tid >> 5;
    const int wm = wid & 3, wn = wid >> 2;
    const int m0 = blockIdx.y * 128, n0 = blockIdx.x * 64;

    const __nv_bfloat16* BP[2] = {A1, A2};

    float acc[16];
#pragma unroll
    for (int c = 0; c < 16; c++) acc[c] = 0.f;

    auto load_stage = [&](int kt, int buf) {
        const uint32_t sb = sbu + buf * G2_STAGE;
        const int k0 = kt * 64;
#pragma unroll
        for (int it = 0; it < 2; it++) {              // Q tile
            int i = tid + it * 512;
            int row = i >> 3, ch = i & 7;
            cpa16(sb + sw(row, ch), Q + (size_t)(m0 + row) * RANK + k0 + ch * 8);
        }
#pragma unroll
        for (int l = 0; l < 2; l++) {                 // A limb tiles
            int row = tid >> 3, ch = tid & 7;
            cpa16(sb + 16384 + l * 8192 + sw(row, ch),
                  BP[l] + (size_t)(n0 + row) * RANK + k0 + ch * 8);
        }
    };

    load_stage(0, 0); cpa_commit();
    load_stage(1, 1); cpa_commit();

    const int tA = lane >> 3, rA = lane & 7;
    const uint32_t arow = wm * 32 + (tA & 1) * 8 + rA;
    const uint32_t brow = wn * 16 + ((lane >> 4) & 1) * 8 + (lane & 7);
    const uint32_t bch  = (lane >> 3) & 1;

    for (int kt = 0; kt < 16; kt++) {
        cpa_wait1();
        __syncthreads();

        const uint32_t sb = sbu + (kt % 3) * G2_STAGE;
        uint32_t aF[2][4][4];
#pragma unroll
        for (int mi = 0; mi < 2; mi++)
#pragma unroll
            for (int ks = 0; ks < 4; ks++)
                ldsm4(aF[mi][ks], sb + sw(arow + mi * 16, ks * 2 + (tA >> 1)));
#pragma unroll
        for (int bl = 1; bl >= 0; bl--) {
            const uint32_t tb = sb + 16384 + bl * 8192;
#pragma unroll
            for (int ks = 0; ks < 4; ks++) {
                uint32_t bF[4];
                ldsm4(bF, tb + sw(brow, ks * 2 + bch));
                mma_bf16(&acc[0],  aF[0][ks], bF + 0);
                mma_bf16(&acc[8],  aF[1][ks], bF + 0);
                mma_bf16(&acc[4],  aF[0][ks], bF + 2);
                mma_bf16(&acc[12], aF[1][ks], bF + 2);
            }
        }

        if (kt + 2 < 16) load_stage(kt + 2, (kt + 2) % 3);
        cpa_commit();
    }

    // ---- epilogue: scale + bias ----
    const float amax  = __int_as_float(g_amax_bits);
    const float scale = __fdiv_rn(fmaxf(amax, 1e-8f), 3.0f);
    const int rbase = m0 + wm * 32 + (lane >> 2);
    const int cbase = n0 + wn * 16 + (lane & 3) * 2;
#pragma unroll
    for (int mi = 0; mi < 2; mi++)
#pragma unroll
        for (int ni = 0; ni < 2; ni++) {
            const float* f = &acc[mi * 8 + ni * 4];
            const int col = cbase + ni * 8;
            const float b0 = __ldg(bias + col), b1 = __ldg(bias + col + 1);
            float* p0 = Out + (size_t)(rbase + mi * 16)     * OUTF + col;
            float* p1 = Out + (size_t)(rbase + mi * 16 + 8) * OUTF + col;
            *reinterpret_cast<float2*>(p0) =
                make_float2(__fadd_rn(__fmul_rn(f[0], scale), b0),
                            __fadd_rn(__fmul_rn(f[1], scale), b1));
            *reinterpret_cast<float2*>(p1) =
                make_float2(__fadd_rn(__fmul_rn(f[2], scale), b0),
                            __fadd_rn(__fmul_rn(f[3], scale), b1));
        }
}

// ---------------------------------------------------------------------------
extern "C" void kernel_launch(void* const* d_in, const int* in_sizes, int n_in,
                              void* d_out, int out_size)
{
    const float* input = (const float*)d_in[0];
    const float* B_w   = (const float*)d_in[1];
    const float* A_w   = (const float*)d_in[2];
    const float* A_b   = (const float*)d_in[3];
    float*       out   = (float*)d_out;

    __nv_bfloat16 *x1, *x2, *x3, *w1, *w2, *w3, *a1, *a2, *q;
    float* y;
    cudaGetSymbolAddress((void**)&x1, g_x1); cudaGetSymbolAddress((void**)&x2, g_x2);
    cudaGetSymbolAddress((void**)&x3, g_x3); cudaGetSymbolAddress((void**)&w1, g_w1);
    cudaGetSymbolAddress((void**)&w2, g_w2); cudaGetSymbolAddress((void**)&w3, g_w3);
    cudaGetSymbolAddress((void**)&a1, g_a1); cudaGetSymbolAddress((void**)&a2, g_a2);
    cudaGetSymbolAddress((void**)&q,  g_q);  cudaGetSymbolAddress((void**)&y,  g_y);

    cudaFuncSetAttribute(gemm1_mma, cudaFuncAttributeMaxDynamicSharedMemorySize, G1_SMEM);
    cudaFuncSetAttribute(gemm2_mma, cudaFuncAttributeMaxDynamicSharedMemorySize, G2_SMEM);

    k_reset<<<1, 1>>>();

    {   // limb splits
        int n2 = TOKENS * INF / 2;
        k_split3<<<(n2 + 255) / 256, 256>>>(input, x1, x2, x3, n2);
        n2 = RANK * INF / 2;
        k_split3<<<(n2 + 255) / 256, 256>>>(B_w, w1, w2, w3, n2);
        n2 = OUTF * RANK / 2;
        k_split2<<<(n2 + 255) / 256, 256>>>(A_w, a1, a2, n2);
    }

    {   // y = x @ B_w^T  (tensor cores, fused amax)
        dim3 grid(RANK / 64, TOKENS / 128);
        gemm1_mma<<<grid, 512, G1_SMEM>>>(x1, x2, x3, w1, w2, w3, y);
    }

    {   // q = clip(round(y/scale))
        const int n2 = TOKENS * RANK / 2;
        k_quant<<<(n2 + 255) / 256, 256>>>(y, q, n2);
    }

    {   // out = q @ A^T * scale + bias
        dim3 grid(OUTF / 64, TOKENS / 128);
        gemm2_mma<<<grid, 512, G2_SMEM>>>(q, a1, a2, A_b, out);
    }
}

// round 9
// speedup vs baseline: 2.8160x; 1.0536x over previous
#include <cuda_runtime.h>
#include <cuda_bf16.h>
#include <cstdint>

constexpr int TOKENS = 8192;
constexpr int INF    = 4096;
constexpr int RANK   = 1024;
constexpr int OUTF   = 4096;

// ---------------- static device scratch (no allocs allowed) ----------------
__device__ __nv_bfloat16 g_x1[(size_t)TOKENS * INF];
__device__ __nv_bfloat16 g_x2[(size_t)TOKENS * INF];
__device__ __nv_bfloat16 g_x3[(size_t)TOKENS * INF];
__device__ __nv_bfloat16 g_w1[(size_t)RANK * INF];
__device__ __nv_bfloat16 g_w2[(size_t)RANK * INF];
__device__ __nv_bfloat16 g_w3[(size_t)RANK * INF];
__device__ __nv_bfloat16 g_a1[(size_t)OUTF * RANK];
__device__ __nv_bfloat16 g_a2[(size_t)OUTF * RANK];
__device__ __nv_bfloat16 g_q [(size_t)TOKENS * RANK];
__device__ float         g_y [(size_t)TOKENS * RANK];
__device__ int           g_amax_bits;

// ---------------- low-level helpers (baseline PTX, sm_80+) ----------------
__device__ __forceinline__ uint32_t smem_u32(const void* p) {
    uint32_t a;
    asm("{ .reg .u64 t; cvta.to.shared.u64 t, %1; cvt.u32.u64 %0, t; }" : "=r"(a) : "l"(p));
    return a;
}
__device__ __forceinline__ void cpa16(uint32_t s, const void* g) {
    asm volatile("cp.async.cg.shared.global [%0], [%1], 16;" :: "r"(s), "l"(g));
}
__device__ __forceinline__ void cpa_commit() { asm volatile("cp.async.commit_group;" ::: "memory"); }
__device__ __forceinline__ void cpa_wait1()  { asm volatile("cp.async.wait_group 1;" ::: "memory"); }

__device__ __forceinline__ void ldsm4(uint32_t* r, uint32_t a) {
    asm volatile("ldmatrix.sync.aligned.m8n8.x4.shared.b16 {%0,%1,%2,%3}, [%4];"
                 : "=r"(r[0]), "=r"(r[1]), "=r"(r[2]), "=r"(r[3]) : "r"(a));
}
__device__ __forceinline__ void mma_bf16(float* d, const uint32_t* a, const uint32_t* b) {
    asm volatile(
        "mma.sync.aligned.m16n8k16.row.col.f32.bf16.bf16.f32 "
        "{%0,%1,%2,%3}, {%4,%5,%6,%7}, {%8,%9}, {%0,%1,%2,%3};"
        : "+f"(d[0]), "+f"(d[1]), "+f"(d[2]), "+f"(d[3])
        : "r"(a[0]), "r"(a[1]), "r"(a[2]), "r"(a[3]), "r"(b[0]), "r"(b[1]));
}
// 128B rows of 8 x 16B chunks; xor-swizzle -> conflict-free ldmatrix & stores
__device__ __forceinline__ uint32_t sw(uint32_t row, uint32_t ch) {
    return row * 128u + ((ch ^ (row & 7u)) * 16u);
}

// ---------------- prep kernels ----------------
__global__ void k_reset() { g_amax_bits = 0; }

__global__ void k_split3(const float* __restrict__ s, __nv_bfloat16* __restrict__ d1,
                         __nv_bfloat16* __restrict__ d2, __nv_bfloat16* __restrict__ d3, int n2) {
    int i = blockIdx.x * blockDim.x + threadIdx.x;
    if (i >= n2) return;
    float2 v = reinterpret_cast<const float2*>(s)[i];
    float f[2] = {v.x, v.y};
    __nv_bfloat16 h1[2], h2[2], h3[2];
#pragma unroll
    for (int j = 0; j < 2; j++) {
        h1[j] = __float2bfloat16_rn(f[j]);
        float r  = __fsub_rn(f[j], __bfloat162float(h1[j]));   // exact
        h2[j] = __float2bfloat16_rn(r);
        float r2 = __fsub_rn(r, __bfloat162float(h2[j]));      // exact
        h3[j] = __float2bfloat16_rn(r2);                       // exact (27>=24 bits)
    }
    reinterpret_cast<__nv_bfloat162*>(d1)[i] = __halves2bfloat162(h1[0], h1[1]);
    reinterpret_cast<__nv_bfloat162*>(d2)[i] = __halves2bfloat162(h2[0], h2[1]);
    reinterpret_cast<__nv_bfloat162*>(d3)[i] = __halves2bfloat162(h3[0], h3[1]);
}

__global__ void k_split2(const float* __restrict__ s, __nv_bfloat16* __restrict__ d1,
                         __nv_bfloat16* __restrict__ d2, int n2) {
    int i = blockIdx.x * blockDim.x + threadIdx.x;
    if (i >= n2) return;
    float2 v = reinterpret_cast<const float2*>(s)[i];
    float f[2] = {v.x, v.y};
    __nv_bfloat16 h1[2], h2[2];
#pragma unroll
    for (int j = 0; j < 2; j++) {
        h1[j] = __float2bfloat16_rn(f[j]);
        float r = __fsub_rn(f[j], __bfloat162float(h1[j]));
        h2[j] = __float2bfloat16_rn(r);
    }
    reinterpret_cast<__nv_bfloat162*>(d1)[i] = __halves2bfloat162(h1[0], h1[1]);
    reinterpret_cast<__nv_bfloat162*>(d2)[i] = __halves2bfloat162(h2[0], h2[1]);
}

// q = clip(round(y/scale), -4, 3), exact small integers in bf16
__global__ void k_quant(const float* __restrict__ y, __nv_bfloat16* __restrict__ q, int n2) {
    const float amax  = __int_as_float(g_amax_bits);
    const float scale = __fdiv_rn(fmaxf(amax, 1e-8f), 3.0f);
    int i = blockIdx.x * blockDim.x + threadIdx.x;
    if (i >= n2) return;
    float2 v = reinterpret_cast<const float2*>(y)[i];
    float q0 = fminf(fmaxf(rintf(__fdiv_rn(v.x, scale)), -4.f), 3.f);
    float q1 = fminf(fmaxf(rintf(__fdiv_rn(v.y, scale)), -4.f), 3.f);
    reinterpret_cast<__nv_bfloat162*>(q)[i] =
        __halves2bfloat162(__float2bfloat16_rn(q0), __float2bfloat16_rn(q1));
}

// ---------------------------------------------------------------------------
// GEMM1: y = x @ B_w^T via 6 limb products on mma.sync bf16.
// Block 128(M)x64(N), BK=64, 256 threads = 8 warps (4m x 2n), warp tile 32x32.
// 3-stage cp.async pipeline, 1 sync/k-tile. Fresh chunk per k-tile (K=64),
// Kahan merge every k-tile. Per-element accumulation order identical to R8.
// ---------------------------------------------------------------------------
constexpr int G1_STAGE = 3 * 16384 + 3 * 8192;   // x limbs (128x64) + w limbs (64x64)
constexpr int G1_SMEM  = 3 * G1_STAGE;           // 216 KB

__global__ __launch_bounds__(256, 1)
void gemm1_mma(const __nv_bfloat16* __restrict__ X1, const __nv_bfloat16* __restrict__ X2,
               const __nv_bfloat16* __restrict__ X3, const __nv_bfloat16* __restrict__ W1,
               const __nv_bfloat16* __restrict__ W2, const __nv_bfloat16* __restrict__ W3,
               float* __restrict__ Y)
{
    extern __shared__ char smem_raw[];
    const uint32_t sbu = smem_u32(smem_raw);
    const int tid = threadIdx.x, lane = tid & 31, wid = tid >> 5;
    const int wm = wid & 3, wn = wid >> 2;        // 4m x 2n
    const int m0 = blockIdx.y * 128, n0 = blockIdx.x * 64;

    const __nv_bfloat16* AP[3] = {X1, X2, X3};
    const __nv_bfloat16* BP[3] = {W1, W2, W3};

    float acc[32], cmp[32];
#pragma unroll
    for (int c = 0; c < 32; c++) { acc[c] = 0.f; cmp[c] = 0.f; }

    auto load_stage = [&](int kt, int buf) {
        const uint32_t sb = sbu + buf * G1_STAGE;
        const int k0 = kt * 64;
#pragma unroll
        for (int l = 0; l < 3; l++) {
#pragma unroll
            for (int it = 0; it < 4; it++) {            // A tile: 1024 chunks
                int i = tid + it * 256;
                int row = i >> 3, ch = i & 7;
                cpa16(sb + l * 16384 + sw(row, ch),
                      AP[l] + (size_t)(m0 + row) * INF + k0 + ch * 8);
            }
#pragma unroll
            for (int it = 0; it < 2; it++) {            // B tile: 512 chunks
                int i = tid + it * 256;
                int row = i >> 3, ch = i & 7;
                cpa16(sb + 49152 + l * 8192 + sw(row, ch),
                      BP[l] + (size_t)(n0 + row) * INF + k0 + ch * 8);
            }
        }
    };

    load_stage(0, 0); cpa_commit();
    load_stage(1, 1); cpa_commit();

    const int tA = lane >> 3, rA = lane & 7;
    const uint32_t arow  = wm * 32 + (tA & 1) * 8 + rA;                    // + mi*16
    const uint32_t brow0 = wn * 32 +      ((lane >> 4) & 1) * 8 + (lane & 7);
    const uint32_t brow1 = wn * 32 + 16 + ((lane >> 4) & 1) * 8 + (lane & 7);
    const uint32_t bch   = (lane >> 3) & 1;                                // + ks*2

    for (int kt = 0; kt < 64; kt++) {
        cpa_wait1();
        __syncthreads();

        const uint32_t sb = sbu + (kt % 3) * G1_STAGE;
        float chunk[32];
#pragma unroll
        for (int c = 0; c < 32; c++) chunk[c] = 0.f;

        // products grouped by A-limb, small-magnitude first, (1,1) last
#pragma unroll
        for (int al = 2; al >= 0; al--) {
            uint32_t aF[2][4][4];
            const uint32_t ta = sb + al * 16384;
#pragma unroll
            for (int mi = 0; mi < 2; mi++)
#pragma unroll
                for (int ks = 0; ks < 4; ks++)
                    ldsm4(aF[mi][ks], ta + sw(arow + mi * 16, ks * 2 + (tA >> 1)));
            const int nb = (al == 0) ? 3 : (al == 1 ? 2 : 1);
#pragma unroll
            for (int bl = 2; bl >= 0; bl--) {
                if (bl >= nb) continue;
                const uint32_t tb = sb + 49152 + bl * 8192;
#pragma unroll
                for (int ks = 0; ks < 4; ks++) {
                    uint32_t bF[4], bG[4];               // [ni lo: k0,k1 | ni hi: k0,k1]
                    ldsm4(bF, tb + sw(brow0, ks * 2 + bch));
                    ldsm4(bG, tb + sw(brow1, ks * 2 + bch));
                    mma_bf16(&chunk[0],  aF[0][ks], bF + 0);
                    mma_bf16(&chunk[16], aF[1][ks], bF + 0);
                    mma_bf16(&chunk[4],  aF[0][ks], bF + 2);
                    mma_bf16(&chunk[20], aF[1][ks], bF + 2);
                    mma_bf16(&chunk[8],  aF[0][ks], bG + 0);
                    mma_bf16(&chunk[24], aF[1][ks], bG + 0);
                    mma_bf16(&chunk[12], aF[0][ks], bG + 2);
                    mma_bf16(&chunk[28], aF[1][ks], bG + 2);
                }
            }
        }

        // Kahan merge every k-tile (IEEE intrinsics; immune to fast-math)
#pragma unroll
        for (int c = 0; c < 32; c++) {
            float yk = __fsub_rn(chunk[c], cmp[c]);
            float t  = __fadd_rn(acc[c], yk);
            cmp[c]   = __fsub_rn(__fsub_rn(t, acc[c]), yk);
            acc[c]   = t;
        }

        if (kt + 2 < 64) load_stage(kt + 2, (kt + 2) % 3);
        cpa_commit();          // empty group at tail keeps wait_group bookkeeping
    }

    // ---- epilogue: fold, amax, store ----
    float v[32];
    float lmax = 0.f;
#pragma unroll
    for (int c = 0; c < 32; c++) {
        v[c] = __fsub_rn(acc[c], cmp[c]);
        lmax = fmaxf(lmax, fabsf(v[c]));
    }
#pragma unroll
    for (int o = 16; o > 0; o >>= 1)
        lmax = fmaxf(lmax, __shfl_xor_sync(0xffffffffu, lmax, o));
    if (lane == 0) atomicMax(&g_amax_bits, __float_as_int(lmax));

    const int rbase = m0 + wm * 32 + (lane >> 2);
    const int cbase = n0 + wn * 32 + (lane & 3) * 2;
#pragma unroll
    for (int mi = 0; mi < 2; mi++)
#pragma unroll
        for (int ni = 0; ni < 4; ni++) {
            const float* f = &v[mi * 16 + ni * 4];
            float* p0 = Y + (size_t)(rbase + mi * 16)     * RANK + cbase + ni * 8;
            float* p1 = Y + (size_t)(rbase + mi * 16 + 8) * RANK + cbase + ni * 8;
            *reinterpret_cast<float2*>(p0) = make_float2(f[0], f[1]);
            *reinterpret_cast<float2*>(p1) = make_float2(f[2], f[3]);
        }
}

// ---------------------------------------------------------------------------
// GEMM2: out = (q @ A^T) * scale + bias, 2 limb products, plain accumulation.
// Block 128x64, BK=64, 256 threads = 8 warps (4m x 2n), warp tile 32x32.
// ---------------------------------------------------------------------------
constexpr int G2_STAGE = 16384 + 2 * 8192;   // q (128x64) + a1,a2 (64x64)
constexpr int G2_SMEM  = 3 * G2_STAGE;       // 96 KB

__global__ __launch_bounds__(256, 1)
void gemm2_mma(const __nv_bfloat16* __restrict__ Q, const __nv_bfloat16* __restrict__ A1,
               const __nv_bfloat16* __restrict__ A2, const float* __restrict__ bias,
               float* __restrict__ Out)
{
    extern __shared__ char smem_raw[];
    const uint32_t sbu = smem_u32(smem_raw);
    const int tid = threadIdx.x, lane = tid & 31, wid = tid >> 5;
    const int wm = wid & 3, wn = wid >> 2;
    const int m0 = blockIdx.y * 128, n0 = blockIdx.x * 64;

    const __nv_bfloat16* BP[2] = {A1, A2};

    float acc[32];
#pragma unroll
    for (int c = 0; c < 32; c++) acc[c] = 0.f;

    auto load_stage = [&](int kt, int buf) {
        const uint32_t sb = sbu + buf * G2_STAGE;
        const int k0 = kt * 64;
#pragma unroll
        for (int it = 0; it < 4; it++) {              // Q tile: 1024 chunks
            int i = tid + it * 256;
            int row = i >> 3, ch = i & 7;
            cpa16(sb + sw(row, ch), Q + (size_t)(m0 + row) * RANK + k0 + ch * 8);
        }
#pragma unroll
        for (int l = 0; l < 2; l++)                    // A limb tiles: 512 each
#pragma unroll
            for (int it = 0; it < 2; it++) {
                int i = tid + it * 256;
                int row = i >> 3, ch = i & 7;
                cpa16(sb + 16384 + l * 8192 + sw(row, ch),
                      BP[l] + (size_t)(n0 + row) * RANK + k0 + ch * 8);
            }
    };

    load_stage(0, 0); cpa_commit();
    load_stage(1, 1); cpa_commit();

    const int tA = lane >> 3, rA = lane & 7;
    const uint32_t arow  = wm * 32 + (tA & 1) * 8 + rA;
    const uint32_t brow0 = wn * 32 +      ((lane >> 4) & 1) * 8 + (lane & 7);
    const uint32_t brow1 = wn * 32 + 16 + ((lane >> 4) & 1) * 8 + (lane & 7);
    const uint32_t bch   = (lane >> 3) & 1;

    for (int kt = 0; kt < 16; kt++) {
        cpa_wait1();
        __syncthreads();

        const uint32_t sb = sbu + (kt % 3) * G2_STAGE;
        uint32_t aF[2][4][4];
#pragma unroll
        for (int mi = 0; mi < 2; mi++)
#pragma unroll
            for (int ks = 0; ks < 4; ks++)
                ldsm4(aF[mi][ks], sb + sw(arow + mi * 16, ks * 2 + (tA >> 1)));
#pragma unroll
        for (int bl = 1; bl >= 0; bl--) {
            const uint32_t tb = sb + 16384 + bl * 8192;
#pragma unroll
            for (int ks = 0; ks < 4; ks++) {
                uint32_t bF[4], bG[4];
                ldsm4(bF, tb + sw(brow0, ks * 2 + bch));
                ldsm4(bG, tb + sw(brow1, ks * 2 + bch));
                mma_bf16(&acc[0],  aF[0][ks], bF + 0);
                mma_bf16(&acc[16], aF[1][ks], bF + 0);
                mma_bf16(&acc[4],  aF[0][ks], bF + 2);
                mma_bf16(&acc[20], aF[1][ks], bF + 2);
                mma_bf16(&acc[8],  aF[0][ks], bG + 0);
                mma_bf16(&acc[24], aF[1][ks], bG + 0);
                mma_bf16(&acc[12], aF[0][ks], bG + 2);
                mma_bf16(&acc[28], aF[1][ks], bG + 2);
            }
        }

        if (kt + 2 < 16) load_stage(kt + 2, (kt + 2) % 3);
        cpa_commit();
    }

    // ---- epilogue: scale + bias ----
    const float amax  = __int_as_float(g_amax_bits);
    const float scale = __fdiv_rn(fmaxf(amax, 1e-8f), 3.0f);
    const int rbase = m0 + wm * 32 + (lane >> 2);
    const int cbase = n0 + wn * 32 + (lane & 3) * 2;
#pragma unroll
    for (int mi = 0; mi < 2; mi++)
#pragma unroll
        for (int ni = 0; ni < 4; ni++) {
            const float* f = &acc[mi * 16 + ni * 4];
            const int col = cbase + ni * 8;
            const float b0 = __ldg(bias + col), b1 = __ldg(bias + col + 1);
            float* p0 = Out + (size_t)(rbase + mi * 16)     * OUTF + col;
            float* p1 = Out + (size_t)(rbase + mi * 16 + 8) * OUTF + col;
            *reinterpret_cast<float2*>(p0) =
                make_float2(__fadd_rn(__fmul_rn(f[0], scale), b0),
                            __fadd_rn(__fmul_rn(f[1], scale), b1));
            *reinterpret_cast<float2*>(p1) =
                make_float2(__fadd_rn(__fmul_rn(f[2], scale), b0),
                            __fadd_rn(__fmul_rn(f[3], scale), b1));
        }
}

// ---------------------------------------------------------------------------
extern "C" void kernel_launch(void* const* d_in, const int* in_sizes, int n_in,
                              void* d_out, int out_size)
{
    const float* input = (const float*)d_in[0];
    const float* B_w   = (const float*)d_in[1];
    const float* A_w   = (const float*)d_in[2];
    const float* A_b   = (const float*)d_in[3];
    float*       out   = (float*)d_out;

    __nv_bfloat16 *x1, *x2, *x3, *w1, *w2, *w3, *a1, *a2, *q;
    float* y;
    cudaGetSymbolAddress((void**)&x1, g_x1); cudaGetSymbolAddress((void**)&x2, g_x2);
    cudaGetSymbolAddress((void**)&x3, g_x3); cudaGetSymbolAddress((void**)&w1, g_w1);
    cudaGetSymbolAddress((void**)&w2, g_w2); cudaGetSymbolAddress((void**)&w3, g_w3);
    cudaGetSymbolAddress((void**)&a1, g_a1); cudaGetSymbolAddress((void**)&a2, g_a2);
    cudaGetSymbolAddress((void**)&q,  g_q);  cudaGetSymbolAddress((void**)&y,  g_y);

    cudaFuncSetAttribute(gemm1_mma, cudaFuncAttributeMaxDynamicSharedMemorySize, G1_SMEM);
    cudaFuncSetAttribute(gemm2_mma, cudaFuncAttributeMaxDynamicSharedMemorySize, G2_SMEM);

    k_reset<<<1, 1>>>();

    {   // limb splits
        int n2 = TOKENS * INF / 2;
        k_split3<<<(n2 + 255) / 256, 256>>>(input, x1, x2, x3, n2);
        n2 = RANK * INF / 2;
        k_split3<<<(n2 + 255) / 256, 256>>>(B_w, w1, w2, w3, n2);
        n2 = OUTF * RANK / 2;
        k_split2<<<(n2 + 255) / 256, 256>>>(A_w, a1, a2, n2);
    }

    {   // y = x @ B_w^T  (tensor cores, fused amax)
        dim3 grid(RANK / 64, TOKENS / 128);
        gemm1_mma<<<grid, 256, G1_SMEM>>>(x1, x2, x3, w1, w2, w3, y);
    }

    {   // q = clip(round(y/scale))
        const int n2 = TOKENS * RANK / 2;
        k_quant<<<(n2 + 255) / 256, 256>>>(y, q, n2);
    }

    {   // out = q @ A^T * scale + bias
        dim3 grid(OUTF / 64, TOKENS / 128);
        gemm2_mma<<<grid, 256, G2_SMEM>>>(q, a1, a2, A_b, out);
    }
}